// round 4
// baseline (speedup 1.0000x reference)
#include <cuda_runtime.h>

#define CC 256           // feature dim (fixed for this problem)
#define MAXB 64          // safety headroom for num_batches

// Scratch: per-(batch, channel) partial sums. Device global (no allocs allowed).
__device__ float g_sums[MAXB * CC];

__global__ void zero_kernel(int n) {
    int i = blockIdx.x * blockDim.x + threadIdx.x;
    if (i < n) g_sums[i] = 0.0f;
}

__device__ __forceinline__ float4 ldcs4(const float* p) {
    return __ldcs(reinterpret_cast<const float4*>(p));
}

// Accumulation: each block owns a contiguous row range [r0, r1).
// 256 threads: thread t handles channels [4*(t&63), +4) of rows r0 + (t>>6) + 4k.
// batch_idx is sorted; segments (~62k rows) are far larger than a block's range
// (~845 rows), so almost every block is single-segment -> branch-free fast path.
__global__ void __launch_bounds__(256) accum_kernel(
    const float* __restrict__ feat,
    const int*   __restrict__ bidx,
    const float* __restrict__ p_ptr,
    int n, int rows_per_block)
{
    const int tid   = threadIdx.x;
    const int c4    = (tid & 63) * 4;
    const int rlane = tid >> 6;                  // 0..3 (warp-uniform)
    int r0 = blockIdx.x * rows_per_block;
    int r1 = r0 + rows_per_block;
    if (r1 > n) r1 = n;
    if (r0 >= n) return;                         // block-uniform

    const float p  = __ldg(p_ptr);
    const bool  p3 = (p == 3.0f);

    const int seg_lo = __ldg(bidx + r0);
    const int seg_hi = __ldg(bidx + r1 - 1);

    float a0 = 0.f, a1 = 0.f, a2 = 0.f, a3 = 0.f;

    if (seg_lo == seg_hi) {
        // ---- fast path: whole block inside one segment ----
        int r = r0 + rlane;
        const size_t stride = (size_t)CC;
        if (p3) {
            // unroll x4: 4 independent 16B loads in flight per thread
            for (; r + 12 < r1; r += 16) {
                const float* base = feat + (size_t)r * stride + c4;
                float4 v0 = ldcs4(base);
                float4 v1 = ldcs4(base + 4 * CC);
                float4 v2 = ldcs4(base + 8 * CC);
                float4 v3 = ldcs4(base + 12 * CC);
                float x;
                x = fmaxf(v0.x, 1e-6f); a0 = fmaf(x * x, x, a0);
                x = fmaxf(v0.y, 1e-6f); a1 = fmaf(x * x, x, a1);
                x = fmaxf(v0.z, 1e-6f); a2 = fmaf(x * x, x, a2);
                x = fmaxf(v0.w, 1e-6f); a3 = fmaf(x * x, x, a3);
                x = fmaxf(v1.x, 1e-6f); a0 = fmaf(x * x, x, a0);
                x = fmaxf(v1.y, 1e-6f); a1 = fmaf(x * x, x, a1);
                x = fmaxf(v1.z, 1e-6f); a2 = fmaf(x * x, x, a2);
                x = fmaxf(v1.w, 1e-6f); a3 = fmaf(x * x, x, a3);
                x = fmaxf(v2.x, 1e-6f); a0 = fmaf(x * x, x, a0);
                x = fmaxf(v2.y, 1e-6f); a1 = fmaf(x * x, x, a1);
                x = fmaxf(v2.z, 1e-6f); a2 = fmaf(x * x, x, a2);
                x = fmaxf(v2.w, 1e-6f); a3 = fmaf(x * x, x, a3);
                x = fmaxf(v3.x, 1e-6f); a0 = fmaf(x * x, x, a0);
                x = fmaxf(v3.y, 1e-6f); a1 = fmaf(x * x, x, a1);
                x = fmaxf(v3.z, 1e-6f); a2 = fmaf(x * x, x, a2);
                x = fmaxf(v3.w, 1e-6f); a3 = fmaf(x * x, x, a3);
            }
            for (; r < r1; r += 4) {
                float4 v = ldcs4(feat + (size_t)r * stride + c4);
                float x;
                x = fmaxf(v.x, 1e-6f); a0 = fmaf(x * x, x, a0);
                x = fmaxf(v.y, 1e-6f); a1 = fmaf(x * x, x, a1);
                x = fmaxf(v.z, 1e-6f); a2 = fmaf(x * x, x, a2);
                x = fmaxf(v.w, 1e-6f); a3 = fmaf(x * x, x, a3);
            }
        } else {
            for (; r < r1; r += 4) {
                float4 v = ldcs4(feat + (size_t)r * stride + c4);
                a0 += powf(fmaxf(v.x, 1e-6f), p);
                a1 += powf(fmaxf(v.y, 1e-6f), p);
                a2 += powf(fmaxf(v.z, 1e-6f), p);
                a3 += powf(fmaxf(v.w, 1e-6f), p);
            }
        }

        // cross-rlane reduction in smem: cut atomics 4x
        __shared__ float sred[4][CC];
        sred[rlane][c4 + 0] = a0;
        sred[rlane][c4 + 1] = a1;
        sred[rlane][c4 + 2] = a2;
        sred[rlane][c4 + 3] = a3;
        __syncthreads();
        if (rlane == 0) {
            float* s = g_sums + seg_lo * CC + c4;
            #pragma unroll
            for (int j = 0; j < 4; j++) {
                float t = sred[0][c4 + j] + sred[1][c4 + j]
                        + sred[2][c4 + j] + sred[3][c4 + j];
                atomicAdd(s + j, t);
            }
        }
    } else {
        // ---- slow path: block spans a segment boundary (rare) ----
        int cur = -1;
        for (int r = r0 + rlane; r < r1; r += 4) {
            int b = __ldg(bidx + r);             // warp-uniform -> broadcast
            if (b != cur) {
                if (cur >= 0) {
                    float* s = g_sums + cur * CC + c4;
                    atomicAdd(s + 0, a0); atomicAdd(s + 1, a1);
                    atomicAdd(s + 2, a2); atomicAdd(s + 3, a3);
                    a0 = a1 = a2 = a3 = 0.f;
                }
                cur = b;
            }
            float4 v = ldcs4(feat + (size_t)r * CC + c4);
            float x0 = fmaxf(v.x, 1e-6f);
            float x1 = fmaxf(v.y, 1e-6f);
            float x2 = fmaxf(v.z, 1e-6f);
            float x3 = fmaxf(v.w, 1e-6f);
            if (p3) {
                a0 = fmaf(x0 * x0, x0, a0);
                a1 = fmaf(x1 * x1, x1, a1);
                a2 = fmaf(x2 * x2, x2, a2);
                a3 = fmaf(x3 * x3, x3, a3);
            } else {
                a0 += powf(x0, p);
                a1 += powf(x1, p);
                a2 += powf(x2, p);
                a3 += powf(x3, p);
            }
        }
        if (cur >= 0) {
            float* s = g_sums + cur * CC + c4;
            atomicAdd(s + 0, a0); atomicAdd(s + 1, a1);
            atomicAdd(s + 2, a2); atomicAdd(s + 3, a3);
        }
    }
}

__device__ __forceinline__ int lower_bound_dev(const int* __restrict__ a, int n, int key) {
    int lo = 0, hi = n;
    while (lo < hi) {
        int mid = (lo + hi) >> 1;
        if (a[mid] < key) lo = mid + 1; else hi = mid;
    }
    return lo;
}

// Finalize: one block per batch row. Counts via binary search on sorted idx,
// mean^(1/p), then block L2 reduction and normalize.
__global__ void __launch_bounds__(CC) finalize_kernel(
    const int*   __restrict__ bidx,
    const float* __restrict__ p_ptr,
    int n, float* __restrict__ out)
{
    const int b = blockIdx.x;
    const int c = threadIdx.x;
    __shared__ float s_cnt;
    __shared__ float s_norm;
    __shared__ float red[CC / 32];

    if (c == 0) {
        int lo = lower_bound_dev(bidx, n, b);
        int hi = lower_bound_dev(bidx, n, b + 1);
        s_cnt = (float)(hi - lo);
    }
    __syncthreads();

    const float p    = __ldg(p_ptr);
    const float mean = g_sums[b * CC + c] / s_cnt;
    const float desc = powf(mean, 1.0f / p);

    float sq = desc * desc;
    #pragma unroll
    for (int o = 16; o; o >>= 1)
        sq += __shfl_xor_sync(0xffffffffu, sq, o);
    if ((c & 31) == 0) red[c >> 5] = sq;
    __syncthreads();
    if (c == 0) {
        float t = 0.f;
        #pragma unroll
        for (int i = 0; i < CC / 32; i++) t += red[i];
        s_norm = fmaxf(sqrtf(t), 1e-12f);
    }
    __syncthreads();

    out[b * CC + c] = desc / s_norm;
}

extern "C" void kernel_launch(void* const* d_in, const int* in_sizes, int n_in,
                              void* d_out, int out_size) {
    const float* feat  = (const float*)d_in[0];
    const float* p_ptr = (const float*)d_in[1];
    const int*   bidx  = (const int*)d_in[2];

    const int n = in_sizes[2];                 // N rows
    const int C = in_sizes[0] / n;             // feature dim (== 256 here)
    int B = out_size / C;                      // num batches
    if (B < 1) B = 1;
    if (B > MAXB) B = MAXB;

    float* out = (float*)d_out;

    // 1) zero scratch sums (must happen every replay)
    int zn = B * C;
    zero_kernel<<<(zn + 255) / 256, 256>>>(zn);

    // 2) accumulate x^p into per-(batch,channel) sums
    const int grid = 1184;                     // 148 SMs * 8 blocks
    const int rpb  = (n + grid - 1) / grid;
    accum_kernel<<<grid, 256>>>(feat, bidx, p_ptr, n, rpb);

    // 3) finalize: mean, pow(1/p), L2 normalize
    finalize_kernel<<<B, CC>>>(bidx, p_ptr, n, out);
}

// round 6
// speedup vs baseline: 1.0718x; 1.0718x over previous
#include <cuda_runtime.h>

#define CC 256           // feature dim (fixed for this problem)
#define MAXB 64          // safety headroom for num_batches

// Scratch: per-(batch, channel) partial sums. Device global (no allocs allowed).
__device__ float g_sums[MAXB * CC];

__global__ void zero_kernel(int n) {
    int i = blockIdx.x * blockDim.x + threadIdx.x;
    if (i < n) g_sums[i] = 0.0f;
}

__device__ __forceinline__ float4 ldg4(const float* p) {
    return __ldg(reinterpret_cast<const float4*>(p));
}

// Accumulation: each block owns a contiguous row range [r0, r1).
// 256 threads: thread t handles channels [4*(t&63), +4) of rows r0 + (t>>6) + 4k.
// batch_idx is sorted; segments (~62k rows) dwarf a block's range (~845 rows),
// so almost every block is single-segment -> branch-free fast path with zero
// bidx traffic in the hot loop.
// __launch_bounds__(256, 8): cap regs at 64 so grid=1184 is exactly ONE wave
// at 8 CTAs/SM on 148 SMs (the R4 regression was occupancy loss -> 2nd wave).
__global__ void __launch_bounds__(256, 8) accum_kernel(
    const float* __restrict__ feat,
    const int*   __restrict__ bidx,
    const float* __restrict__ p_ptr,
    int n, int rows_per_block)
{
    const int tid   = threadIdx.x;
    const int c4    = (tid & 63) * 4;
    const int rlane = tid >> 6;                  // 0..3 (warp-uniform)
    int r0 = blockIdx.x * rows_per_block;
    int r1 = r0 + rows_per_block;
    if (r1 > n) r1 = n;
    if (r0 >= n) return;                         // block-uniform

    const float p  = __ldg(p_ptr);
    const bool  p3 = (p == 3.0f);

    const int seg_lo = __ldg(bidx + r0);
    const int seg_hi = __ldg(bidx + r1 - 1);

    float a0 = 0.f, a1 = 0.f, a2 = 0.f, a3 = 0.f;

    if (seg_lo == seg_hi) {
        // ---- fast path: whole block inside one segment ----
        if (p3) {
            for (int r = r0 + rlane; r < r1; r += 4) {
                float4 v = ldg4(feat + (size_t)r * CC + c4);
                float x;
                x = fmaxf(v.x, 1e-6f); a0 = fmaf(x * x, x, a0);
                x = fmaxf(v.y, 1e-6f); a1 = fmaf(x * x, x, a1);
                x = fmaxf(v.z, 1e-6f); a2 = fmaf(x * x, x, a2);
                x = fmaxf(v.w, 1e-6f); a3 = fmaf(x * x, x, a3);
            }
        } else {
            for (int r = r0 + rlane; r < r1; r += 4) {
                float4 v = ldg4(feat + (size_t)r * CC + c4);
                a0 += powf(fmaxf(v.x, 1e-6f), p);
                a1 += powf(fmaxf(v.y, 1e-6f), p);
                a2 += powf(fmaxf(v.z, 1e-6f), p);
                a3 += powf(fmaxf(v.w, 1e-6f), p);
            }
        }

        // cross-rlane reduction in smem: cut atomics 4x
        __shared__ float sred[4][CC];
        sred[rlane][c4 + 0] = a0;
        sred[rlane][c4 + 1] = a1;
        sred[rlane][c4 + 2] = a2;
        sred[rlane][c4 + 3] = a3;
        __syncthreads();
        if (rlane == 0) {
            float* s = g_sums + seg_lo * CC + c4;
            #pragma unroll
            for (int j = 0; j < 4; j++) {
                float t = sred[0][c4 + j] + sred[1][c4 + j]
                        + sred[2][c4 + j] + sred[3][c4 + j];
                atomicAdd(s + j, t);
            }
        }
    } else {
        // ---- slow path: block spans a segment boundary (rare) ----
        int cur = -1;
        for (int r = r0 + rlane; r < r1; r += 4) {
            int b = __ldg(bidx + r);             // warp-uniform -> broadcast
            if (b != cur) {
                if (cur >= 0) {
                    float* s = g_sums + cur * CC + c4;
                    atomicAdd(s + 0, a0); atomicAdd(s + 1, a1);
                    atomicAdd(s + 2, a2); atomicAdd(s + 3, a3);
                    a0 = a1 = a2 = a3 = 0.f;
                }
                cur = b;
            }
            float4 v = ldg4(feat + (size_t)r * CC + c4);
            float x0 = fmaxf(v.x, 1e-6f);
            float x1 = fmaxf(v.y, 1e-6f);
            float x2 = fmaxf(v.z, 1e-6f);
            float x3 = fmaxf(v.w, 1e-6f);
            if (p3) {
                a0 = fmaf(x0 * x0, x0, a0);
                a1 = fmaf(x1 * x1, x1, a1);
                a2 = fmaf(x2 * x2, x2, a2);
                a3 = fmaf(x3 * x3, x3, a3);
            } else {
                a0 += powf(x0, p);
                a1 += powf(x1, p);
                a2 += powf(x2, p);
                a3 += powf(x3, p);
            }
        }
        if (cur >= 0) {
            float* s = g_sums + cur * CC + c4;
            atomicAdd(s + 0, a0); atomicAdd(s + 1, a1);
            atomicAdd(s + 2, a2); atomicAdd(s + 3, a3);
        }
    }
}

__device__ __forceinline__ int lower_bound_dev(const int* __restrict__ a, int n, int key) {
    int lo = 0, hi = n;
    while (lo < hi) {
        int mid = (lo + hi) >> 1;
        if (a[mid] < key) lo = mid + 1; else hi = mid;
    }
    return lo;
}

// Finalize: one block per batch row. Counts via binary search on sorted idx,
// mean^(1/p), then block L2 reduction and normalize.
__global__ void __launch_bounds__(CC) finalize_kernel(
    const int*   __restrict__ bidx,
    const float* __restrict__ p_ptr,
    int n, float* __restrict__ out)
{
    const int b = blockIdx.x;
    const int c = threadIdx.x;
    __shared__ float s_cnt;
    __shared__ float s_norm;
    __shared__ float red[CC / 32];

    if (c == 0) {
        int lo = lower_bound_dev(bidx, n, b);
        int hi = lower_bound_dev(bidx, n, b + 1);
        s_cnt = (float)(hi - lo);
    }
    __syncthreads();

    const float p    = __ldg(p_ptr);
    const float mean = g_sums[b * CC + c] / s_cnt;
    const float desc = powf(mean, 1.0f / p);

    float sq = desc * desc;
    #pragma unroll
    for (int o = 16; o; o >>= 1)
        sq += __shfl_xor_sync(0xffffffffu, sq, o);
    if ((c & 31) == 0) red[c >> 5] = sq;
    __syncthreads();
    if (c == 0) {
        float t = 0.f;
        #pragma unroll
        for (int i = 0; i < CC / 32; i++) t += red[i];
        s_norm = fmaxf(sqrtf(t), 1e-12f);
    }
    __syncthreads();

    out[b * CC + c] = desc / s_norm;
}

extern "C" void kernel_launch(void* const* d_in, const int* in_sizes, int n_in,
                              void* d_out, int out_size) {
    const float* feat  = (const float*)d_in[0];
    const float* p_ptr = (const float*)d_in[1];
    const int*   bidx  = (const int*)d_in[2];

    const int n = in_sizes[2];                 // N rows
    const int C = in_sizes[0] / n;             // feature dim (== 256 here)
    int B = out_size / C;                      // num batches
    if (B < 1) B = 1;
    if (B > MAXB) B = MAXB;

    float* out = (float*)d_out;

    // 1) zero scratch sums (must happen every replay)
    int zn = B * C;
    zero_kernel<<<(zn + 255) / 256, 256>>>(zn);

    // 2) accumulate x^p into per-(batch,channel) sums
    const int grid = 1184;                     // 148 SMs * 8 blocks = exactly 1 wave
    const int rpb  = (n + grid - 1) / grid;
    accum_kernel<<<grid, 256>>>(feat, bidx, p_ptr, n, rpb);

    // 3) finalize: mean, pow(1/p), L2 normalize
    finalize_kernel<<<B, CC>>>(bidx, p_ptr, n, out);
}

// round 10
// speedup vs baseline: 1.1540x; 1.0767x over previous
#include <cuda_runtime.h>

#define CC 256           // feature dim (fixed for this problem)
#define MAXB 64          // safety headroom for num_batches

// Scratch: per-(batch, channel) partial sums. Statically zero-initialized at
// module load; finalize_kernel re-zeroes after reading, so no zero pass needed.
__device__ float g_sums[MAXB * CC];

// Accumulation: each block owns a contiguous row range [r0, r1).
// 256 threads: thread t handles channels [4*(t&63), +4) of rows r0 + (t>>6) + 4k.
// batch_idx is sorted, so per-thread the segment id changes rarely: keep a
// register accumulator and flush to global atomics (REDG) only on change/exit.
// NOTE: this exact loop structure (dependent bidx load + branch, plain float4
// deref, direct atomics, no min-blocks bound) measured 180.7us; restructured
// variants (unroll, __ldcs/__ldg, smem reduction, launch_bounds(256,8))
// measured 225-241us. Do not "simplify" it.
__global__ void __launch_bounds__(256) accum_kernel(
    const float* __restrict__ feat,
    const int*   __restrict__ bidx,
    const float* __restrict__ p_ptr,
    int n, int rows_per_block)
{
    const int c4    = (threadIdx.x & 63) * 4;
    const int rlane = threadIdx.x >> 6;          // 0..3 (warp-uniform)
    int r0 = blockIdx.x * rows_per_block;
    int r1 = r0 + rows_per_block;
    if (r1 > n) r1 = n;
    if (r0 >= n) return;

    const float p  = __ldg(p_ptr);
    const bool  p3 = (p == 3.0f);

    float a0 = 0.f, a1 = 0.f, a2 = 0.f, a3 = 0.f;
    int cur = -1;

    #pragma unroll 1
    for (int r = r0 + rlane; r < r1; r += 4) {
        int b = __ldg(bidx + r);                 // warp-uniform -> broadcast
        if (b != cur) {
            if (cur >= 0) {
                float* s = g_sums + cur * CC + c4;
                atomicAdd(s + 0, a0); atomicAdd(s + 1, a1);
                atomicAdd(s + 2, a2); atomicAdd(s + 3, a3);
                a0 = a1 = a2 = a3 = 0.f;
            }
            cur = b;
        }
        float4 v = *reinterpret_cast<const float4*>(feat + (size_t)r * CC + c4);
        float x0 = fmaxf(v.x, 1e-6f);
        float x1 = fmaxf(v.y, 1e-6f);
        float x2 = fmaxf(v.z, 1e-6f);
        float x3 = fmaxf(v.w, 1e-6f);
        if (p3) {  // fast path: 2 FMUL/elem, fully hidden under HBM traffic
            a0 += x0 * x0 * x0;
            a1 += x1 * x1 * x1;
            a2 += x2 * x2 * x2;
            a3 += x3 * x3 * x3;
        } else {   // general path (correctness for arbitrary p)
            a0 += powf(x0, p);
            a1 += powf(x1, p);
            a2 += powf(x2, p);
            a3 += powf(x3, p);
        }
    }
    if (cur >= 0) {
        float* s = g_sums + cur * CC + c4;
        atomicAdd(s + 0, a0); atomicAdd(s + 1, a1);
        atomicAdd(s + 2, a2); atomicAdd(s + 3, a3);
    }
}

__device__ __forceinline__ int lower_bound_dev(const int* __restrict__ a, int n, int key) {
    int lo = 0, hi = n;
    while (lo < hi) {
        int mid = (lo + hi) >> 1;
        if (a[mid] < key) lo = mid + 1; else hi = mid;
    }
    return lo;
}

// Finalize: one block per batch row. Counts via binary search on sorted idx,
// mean^(1/p), then block L2 reduction and normalize. Also re-zeroes g_sums
// after reading so the next graph replay starts clean (replaces zero_kernel).
__global__ void __launch_bounds__(CC) finalize_kernel(
    const int*   __restrict__ bidx,
    const float* __restrict__ p_ptr,
    int n, float* __restrict__ out)
{
    const int b = blockIdx.x;
    const int c = threadIdx.x;
    __shared__ float s_cnt;
    __shared__ float s_norm;
    __shared__ float red[CC / 32];

    if (c == 0) {
        int lo = lower_bound_dev(bidx, n, b);
        int hi = lower_bound_dev(bidx, n, b + 1);
        s_cnt = (float)(hi - lo);
    }
    __syncthreads();

    const float p    = __ldg(p_ptr);
    const float mean = g_sums[b * CC + c] / s_cnt;
    g_sums[b * CC + c] = 0.0f;                  // reset for next replay
    const float desc = powf(mean, 1.0f / p);

    float sq = desc * desc;
    #pragma unroll
    for (int o = 16; o; o >>= 1)
        sq += __shfl_xor_sync(0xffffffffu, sq, o);
    if ((c & 31) == 0) red[c >> 5] = sq;
    __syncthreads();
    if (c == 0) {
        float t = 0.f;
        #pragma unroll
        for (int i = 0; i < CC / 32; i++) t += red[i];
        s_norm = fmaxf(sqrtf(t), 1e-12f);
    }
    __syncthreads();

    out[b * CC + c] = desc / s_norm;
}

extern "C" void kernel_launch(void* const* d_in, const int* in_sizes, int n_in,
                              void* d_out, int out_size) {
    const float* feat  = (const float*)d_in[0];
    const float* p_ptr = (const float*)d_in[1];
    const int*   bidx  = (const int*)d_in[2];

    const int n = in_sizes[2];                 // N rows
    const int C = in_sizes[0] / n;             // feature dim (== 256 here)
    int B = out_size / C;                      // num batches
    if (B < 1) B = 1;
    if (B > MAXB) B = MAXB;

    float* out = (float*)d_out;

    // 1) accumulate x^p into per-(batch,channel) sums.
    //    grid = 2 waves of 148 SMs * 8 blocks: wave>=2 is HW work-stealing,
    //    which evens out the between-SM L2-die finish-time spread of wave 1.
    const int grid = 2368;
    const int rpb  = (n + grid - 1) / grid;
    accum_kernel<<<grid, 256>>>(feat, bidx, p_ptr, n, rpb);

    // 2) finalize: mean, pow(1/p), L2 normalize, and reset sums for next replay
    finalize_kernel<<<B, CC>>>(bidx, p_ptr, n, out);
}

// round 12
// speedup vs baseline: 1.3689x; 1.1863x over previous
#include <cuda_runtime.h>

#define CC 256           // feature dim (fixed for this problem)
#define MAXB 64          // safety headroom for num_batches

// Scratch: statically zero-initialized at module load; finalize_kernel
// re-zeroes after reading, so no zero pass is needed per replay.
__device__ float g_sums[MAXB * CC];
__device__ float g_counts[MAXB];

// Accumulation: each block owns a contiguous row range [r0, r1).
// 256 threads: thread t handles channels [4*(t&63), +4) of rows r0 + (t>>6) + 4k.
// batch_idx is sorted, so per-thread the segment id changes rarely: keep a
// register accumulator and flush to global atomics (REDG) only on change/exit.
// Threads with (tid&63)==0 (rlane 0..3, together covering every row exactly
// once) additionally count rows per segment into g_counts, replacing the
// 16.5us serial binary search that finalize used to do.
// NOTE: this loop structure (dependent bidx load + branch, plain float4
// deref, direct atomics, no min-blocks bound, grid=1184) measured fastest;
// restructured variants (unroll, __ldcs, smem reduction, launch_bounds(256,8),
// grid=2368) measured 209-241us. Do not "simplify" it.
__global__ void __launch_bounds__(256) accum_kernel(
    const float* __restrict__ feat,
    const int*   __restrict__ bidx,
    const float* __restrict__ p_ptr,
    int n, int rows_per_block)
{
    const int  c4      = (threadIdx.x & 63) * 4;
    const int  rlane   = threadIdx.x >> 6;        // 0..3 (warp-uniform)
    const bool counter = (threadIdx.x & 63) == 0; // 4 threads/block count rows
    int r0 = blockIdx.x * rows_per_block;
    int r1 = r0 + rows_per_block;
    if (r1 > n) r1 = n;
    if (r0 >= n) return;

    const float p  = __ldg(p_ptr);
    const bool  p3 = (p == 3.0f);

    float a0 = 0.f, a1 = 0.f, a2 = 0.f, a3 = 0.f;
    float cnt = 0.f;
    int cur = -1;

    #pragma unroll 1
    for (int r = r0 + rlane; r < r1; r += 4) {
        int b = __ldg(bidx + r);                 // warp-uniform -> broadcast
        if (b != cur) {
            if (cur >= 0) {
                float* s = g_sums + cur * CC + c4;
                atomicAdd(s + 0, a0); atomicAdd(s + 1, a1);
                atomicAdd(s + 2, a2); atomicAdd(s + 3, a3);
                a0 = a1 = a2 = a3 = 0.f;
                if (counter) { atomicAdd(g_counts + cur, cnt); cnt = 0.f; }
            }
            cur = b;
        }
        cnt += 1.0f;
        float4 v = *reinterpret_cast<const float4*>(feat + (size_t)r * CC + c4);
        float x0 = fmaxf(v.x, 1e-6f);
        float x1 = fmaxf(v.y, 1e-6f);
        float x2 = fmaxf(v.z, 1e-6f);
        float x3 = fmaxf(v.w, 1e-6f);
        if (p3) {  // fast path: 2 FMUL/elem, fully hidden under HBM traffic
            a0 += x0 * x0 * x0;
            a1 += x1 * x1 * x1;
            a2 += x2 * x2 * x2;
            a3 += x3 * x3 * x3;
        } else {   // general path (correctness for arbitrary p)
            a0 += powf(x0, p);
            a1 += powf(x1, p);
            a2 += powf(x2, p);
            a3 += powf(x3, p);
        }
    }
    if (cur >= 0) {
        float* s = g_sums + cur * CC + c4;
        atomicAdd(s + 0, a0); atomicAdd(s + 1, a1);
        atomicAdd(s + 2, a2); atomicAdd(s + 3, a3);
        if (counter) atomicAdd(g_counts + cur, cnt);
    }
}

// Finalize: one block per batch row. Uses g_counts (accumulated alongside the
// sums) instead of binary-searching bidx — removes ~14us of serial dependent
// DRAM loads. Re-zeroes scratch after reading for the next graph replay.
__global__ void __launch_bounds__(CC) finalize_kernel(
    const float* __restrict__ p_ptr,
    float* __restrict__ out)
{
    const int b = blockIdx.x;
    const int c = threadIdx.x;
    __shared__ float s_norm;
    __shared__ float red[CC / 32];

    const float p    = __ldg(p_ptr);
    const float cntv = g_counts[b];
    const float mean = g_sums[b * CC + c] / cntv;
    g_sums[b * CC + c] = 0.0f;                  // reset for next replay
    if (c == 0) g_counts[b] = 0.0f;
    const float desc = powf(mean, 1.0f / p);

    float sq = desc * desc;
    #pragma unroll
    for (int o = 16; o; o >>= 1)
        sq += __shfl_xor_sync(0xffffffffu, sq, o);
    if ((c & 31) == 0) red[c >> 5] = sq;
    __syncthreads();
    if (c == 0) {
        float t = 0.f;
        #pragma unroll
        for (int i = 0; i < CC / 32; i++) t += red[i];
        s_norm = fmaxf(sqrtf(t), 1e-12f);
    }
    __syncthreads();

    out[b * CC + c] = desc / s_norm;
}

extern "C" void kernel_launch(void* const* d_in, const int* in_sizes, int n_in,
                              void* d_out, int out_size) {
    const float* feat  = (const float*)d_in[0];
    const float* p_ptr = (const float*)d_in[1];
    const int*   bidx  = (const int*)d_in[2];

    const int n = in_sizes[2];                 // N rows
    const int C = in_sizes[0] / n;             // feature dim (== 256 here)
    int B = out_size / C;                      // num batches
    if (B < 1) B = 1;
    if (B > MAXB) B = MAXB;

    float* out = (float*)d_out;

    // 1) accumulate x^p (and row counts) into per-(batch,channel) sums.
    //    grid = 1184 = 148 SMs * 8 blocks (single wave) — measured fastest.
    const int grid = 1184;
    const int rpb  = (n + grid - 1) / grid;
    accum_kernel<<<grid, 256>>>(feat, bidx, p_ptr, n, rpb);

    // 2) finalize: mean, pow(1/p), L2 normalize, reset scratch for next replay
    finalize_kernel<<<B, CC>>>(p_ptr, out);
}